// round 10
// baseline (speedup 1.0000x reference)
#include <cuda_runtime.h>
#include <cuda_bf16.h>
#include <math.h>

// ---------------------------------------------------------------------------
// Problem constants
// ---------------------------------------------------------------------------
#define NF   128          // frames
#define PP   576          // patches
#define DD   1536         // feature dim
#define LM   4096
#define NQ   64
#define PG   9            // patches per pool group (576/64)
#define NM1  127          // N-1
#define NCUBES 8

#define OUT_GATE 0
#define OUT_TH   254
#define OUT_Z    (254 + NQ * LM)   // 262398
// total out = 262526

// ---------------------------------------------------------------------------
// Scratch (static __device__ arrays; no allocation)
// ---------------------------------------------------------------------------
__device__ float g_framepool[(size_t)NF * NQ * DD];   // per-frame per-group patch sums (50 MB)
__device__ float g_framemean[NF * DD];
__device__ float g_mommean[NF * DD];                  // rows 0..126 used
__device__ float g_feat[NF * DD];
__device__ float g_xn[NF * DD];
__device__ float g_h[NF * DD];
__device__ float g_pooled[NQ * DD];
__device__ float g_part[4 * NQ * LM];                 // split-K partials (max 4*64*4096 = 4 MB)
__device__ float g_y[NM1];
__device__ int   g_selidx[PG];
__device__ float g_selw[PG];
__device__ float g_scale;

// ---------------------------------------------------------------------------
// K1: stream video_features once -> framepool[n][g][d] = sum of 9 patches
// grid (64, 128), 384 threads, float4 per thread
// ---------------------------------------------------------------------------
__global__ void __launch_bounds__(384) pool_kernel(const float* __restrict__ vf) {
    int g = blockIdx.x;
    int n = blockIdx.y;
    int d4 = threadIdx.x;                 // 0..383 (x4 floats = 1536)
    const float4* base = (const float4*)(vf + ((size_t)n * PP + (size_t)g * PG) * DD);
    float4 s = make_float4(0.f, 0.f, 0.f, 0.f);
#pragma unroll
    for (int r = 0; r < PG; r++) {
        float4 v = base[(size_t)r * (DD / 4) + d4];
        s.x += v.x; s.y += v.y; s.z += v.z; s.w += v.w;
    }
    float4* dst = (float4*)(g_framepool + ((size_t)n * NQ + g) * DD);
    dst[d4] = s;
}

// ---------------------------------------------------------------------------
// K2: framemean[n][d] = sum_g framepool[n][g][d] / 576
// ---------------------------------------------------------------------------
__global__ void __launch_bounds__(384) mean_kernel() {
    int n = blockIdx.x;
    int d4 = threadIdx.x;
    const float4* src = (const float4*)(g_framepool + (size_t)n * NQ * DD);
    float4 s = make_float4(0.f, 0.f, 0.f, 0.f);
#pragma unroll 8
    for (int g = 0; g < NQ; g++) {
        float4 v = src[(size_t)g * (DD / 4) + d4];
        s.x += v.x; s.y += v.y; s.z += v.z; s.w += v.w;
    }
    const float inv = 1.0f / (float)PP;
    s.x *= inv; s.y *= inv; s.z *= inv; s.w *= inv;
    ((float4*)(g_framemean + n * DD))[d4] = s;
}

// ---------------------------------------------------------------------------
// K3: momentum EMA scan over frame-diffs of framemean
// mom[0] = fm[1]-fm[0]; mom[i] = 0.5*(fm[i+1]-fm[i]) + 0.5*mom[i-1]
// ---------------------------------------------------------------------------
__global__ void scan_kernel() {
    int d = blockIdx.x * blockDim.x + threadIdx.x;
    if (d >= DD) return;
    float fm_prev = g_framemean[d];
    float fm_cur  = g_framemean[DD + d];
    float m = fm_cur - fm_prev;
    g_mommean[d] = m;
    for (int i = 1; i < NM1; i++) {
        fm_prev = fm_cur;
        fm_cur = g_framemean[(i + 1) * DD + d];
        float diff = fm_cur - fm_prev;
        m = 0.5f * diff + 0.5f * m;
        g_mommean[i * DD + d] = m;
    }
}

// ---------------------------------------------------------------------------
// Split-K fp32 GEMM: part[z] = A[M,K-chunk] @ B[K-chunk,N]
// BM=32, BN=128, BK=32, 256 threads, 4x4 microtile, deterministic partials.
// ---------------------------------------------------------------------------
#define BM 32
#define BN 128
#define BK 32
__global__ void __launch_bounds__(256) gemm_splitk(
    const float* __restrict__ A, const float* __restrict__ B,
    float* __restrict__ Cpart, int M, int N, int K)
{
    __shared__ float As[BK][BM];
    __shared__ float Bs[BK][BN];
    int tid = threadIdx.x;
    int n0 = blockIdx.x * BN;
    int m0 = blockIdx.y * BM;
    int splitk = gridDim.z;
    int kchunk = K / splitk;
    int k0 = blockIdx.z * kchunk;
    int ksteps = kchunk / BK;

    int ty = tid >> 5;            // 0..7 -> rows ty*4..ty*4+3
    int tx = tid & 31;            // 0..31 -> cols tx*4..tx*4+3
    int a_m = tid >> 3;           // 0..31
    int a_k = (tid & 7) * 4;      // 0..28
    int b_r = tid >> 5;           // 0..7
    int b_c = (tid & 31) * 4;     // 0..124

    float acc[4][4] = {};

    for (int kt = 0; kt < ksteps; kt++) {
        int kbase = k0 + kt * BK;
        // load A tile (guard M)
        float4 av = make_float4(0.f, 0.f, 0.f, 0.f);
        int mg = m0 + a_m;
        if (mg < M) av = *(const float4*)&A[(size_t)mg * K + kbase + a_k];
        As[a_k + 0][a_m] = av.x;
        As[a_k + 1][a_m] = av.y;
        As[a_k + 2][a_m] = av.z;
        As[a_k + 3][a_m] = av.w;
        // load B tile
#pragma unroll
        for (int j = 0; j < 4; j++) {
            int kr = b_r + j * 8;
            *(float4*)&Bs[kr][b_c] =
                *(const float4*)&B[(size_t)(kbase + kr) * N + n0 + b_c];
        }
        __syncthreads();
#pragma unroll
        for (int kk = 0; kk < BK; kk++) {
            float4 a = *(const float4*)&As[kk][ty * 4];
            float4 b = *(const float4*)&Bs[kk][tx * 4];
            float ar[4] = {a.x, a.y, a.z, a.w};
            float br[4] = {b.x, b.y, b.z, b.w};
#pragma unroll
            for (int i = 0; i < 4; i++)
#pragma unroll
                for (int j = 0; j < 4; j++)
                    acc[i][j] = fmaf(ar[i], br[j], acc[i][j]);
        }
        __syncthreads();
    }

    size_t MN = (size_t)M * N;
    float* base = Cpart + (size_t)blockIdx.z * MN;
#pragma unroll
    for (int i = 0; i < 4; i++) {
        int mg = m0 + ty * 4 + i;
        if (mg < M) {
            float4 v = make_float4(acc[i][0], acc[i][1], acc[i][2], acc[i][3]);
            *(float4*)&base[(size_t)mg * N + n0 + tx * 4] = v;
        }
    }
}

// ---------------------------------------------------------------------------
// Combine split-K partials + bias (+ optional exact GELU)
// ---------------------------------------------------------------------------
__global__ void combine_kernel(const float* __restrict__ part,
                               const float* __restrict__ bias,
                               float* __restrict__ dst,
                               int M, int N, int splitk, int do_gelu)
{
    int idx = blockIdx.x * blockDim.x + threadIdx.x;
    int total = M * N;
    if (idx >= total) return;
    float v = bias[idx % N];
    size_t MN = (size_t)total;
    for (int z = 0; z < splitk; z++) v += part[(size_t)z * MN + idx];
    if (do_gelu) v = 0.5f * v * (1.0f + erff(v * 0.70710678118654752f));
    dst[idx] = v;
}

// ---------------------------------------------------------------------------
// LayerNorm over feat rows -> xn
// ---------------------------------------------------------------------------
__global__ void __launch_bounds__(256) ln_kernel(const float* __restrict__ ln_g,
                                                 const float* __restrict__ ln_b)
{
    int row = blockIdx.x;
    const float* x = g_feat + row * DD;
    float s = 0.f, ss = 0.f;
    for (int d = threadIdx.x; d < DD; d += 256) {
        float v = x[d];
        s += v;
        ss = fmaf(v, v, ss);
    }
    __shared__ float sh1[8], sh2[8];
    int lane = threadIdx.x & 31, w = threadIdx.x >> 5;
#pragma unroll
    for (int o = 16; o; o >>= 1) {
        s  += __shfl_xor_sync(0xFFFFFFFFu, s, o);
        ss += __shfl_xor_sync(0xFFFFFFFFu, ss, o);
    }
    if (lane == 0) { sh1[w] = s; sh2[w] = ss; }
    __syncthreads();
    if (w == 0) {
        s  = (lane < 8) ? sh1[lane] : 0.f;
        ss = (lane < 8) ? sh2[lane] : 0.f;
#pragma unroll
        for (int o = 4; o; o >>= 1) {
            s  += __shfl_xor_sync(0xFFFFFFFFu, s, o);
            ss += __shfl_xor_sync(0xFFFFFFFFu, ss, o);
        }
        if (lane == 0) { sh1[0] = s; sh2[0] = ss; }
    }
    __syncthreads();
    float mu  = sh1[0] * (1.0f / DD);
    float var = sh2[0] * (1.0f / DD) - mu * mu;
    float rstd = rsqrtf(var + 1e-5f);
    for (int d = threadIdx.x; d < DD; d += 256)
        g_xn[row * DD + d] = (x[d] - mu) * rstd * ln_g[d] + ln_b[d];
}

// ---------------------------------------------------------------------------
// Gate head: gate_logits = h @ W2 + b2 ; y = softmax((logits + g*0.1)/0.5)[1]
// grid 127, 64 threads (warp w handles output column w)
// ---------------------------------------------------------------------------
__global__ void __launch_bounds__(64) gate_kernel(const float* __restrict__ W2,
                                                  const float* __restrict__ b2,
                                                  const float* __restrict__ gu,
                                                  float* __restrict__ out)
{
    int row = blockIdx.x;
    int w = threadIdx.x >> 5, lane = threadIdx.x & 31;
    const float* hrow = g_h + row * DD;
    float s = 0.f;
    for (int d = lane; d < DD; d += 32)
        s = fmaf(hrow[d], W2[d * 2 + w], s);
#pragma unroll
    for (int o = 16; o; o >>= 1) s += __shfl_xor_sync(0xFFFFFFFFu, s, o);
    __shared__ float sl[2];
    if (lane == 0) sl[w] = s + b2[w];
    __syncthreads();
    if (threadIdx.x == 0) {
        float l0 = sl[0], l1 = sl[1];
        out[OUT_GATE + row * 2 + 0] = l0;
        out[OUT_GATE + row * 2 + 1] = l1;
        float u0 = gu[row * 2 + 0], u1 = gu[row * 2 + 1];
        float g0 = -logf(-logf(u0 + 1e-20f) + 1e-20f);
        float g1 = -logf(-logf(u1 + 1e-20f) + 1e-20f);
        float a0 = (l0 + g0 * 0.1f) * 2.0f;   // / TEMP(0.5)
        float a1 = (l1 + g1 * 0.1f) * 2.0f;
        float mx = fmaxf(a0, a1);
        float e0 = expf(a0 - mx), e1 = expf(a1 - mx);
        g_y[row] = e1 / (e0 + e1);
    }
}

// ---------------------------------------------------------------------------
// Top-8 selection (stable: max value, lowest index on ties), z_hard, weights
// ---------------------------------------------------------------------------
__global__ void __launch_bounds__(128) topk_kernel(float* __restrict__ out) {
    __shared__ float yv[128];
    __shared__ float rv[128];
    __shared__ int   ri[128];
    __shared__ int   taken[128];
    int t = threadIdx.x;
    yv[t] = (t < NM1) ? g_y[t] : -1e30f;
    taken[t] = 0;
    __syncthreads();
    for (int it = 0; it < NCUBES; it++) {
        rv[t] = taken[t] ? -1e30f : yv[t];
        ri[t] = t;
        __syncthreads();
        for (int off = 64; off > 0; off >>= 1) {
            if (t < off) {
                float v2 = rv[t + off]; int i2 = ri[t + off];
                if (v2 > rv[t] || (v2 == rv[t] && i2 < ri[t])) { rv[t] = v2; ri[t] = i2; }
            }
            __syncthreads();
        }
        if (t == 0) taken[ri[0]] = 1;
        __syncthreads();
    }
    // z_hard output (forward value of straight-through)
    float z = 0.f;
    if (t < NM1) z = taken[t] ? ((1.0f - yv[t]) + yv[t]) : 0.0f;
    if (t == 0) out[OUT_Z] = 1.0f;
    if (t < NM1) out[OUT_Z + 1 + t] = z;
    // sum z
    rv[t] = z;
    __syncthreads();
    for (int off = 64; off > 0; off >>= 1) {
        if (t < off) rv[t] += rv[t + off];
        __syncthreads();
    }
    if (t == 0) {
        float zsum = 1.0f + rv[0];
        g_scale = 1.0f / ((float)PG * zsum);
        g_selidx[0] = 0; g_selw[0] = 1.0f;
        int c = 1;
        for (int i = 0; i < NM1; i++) {
            if (taken[i]) {
                g_selidx[c] = i + 1;
                g_selw[c] = (1.0f - yv[i]) + yv[i];
                c++;
            }
        }
    }
}

// ---------------------------------------------------------------------------
// pooled[g][d] = scale * sum_k w_k * framepool[sel_k][g][d]
// ---------------------------------------------------------------------------
__global__ void __launch_bounds__(384) pooled_kernel() {
    int g = blockIdx.x;
    int d4 = threadIdx.x;
    float4 acc = make_float4(0.f, 0.f, 0.f, 0.f);
#pragma unroll
    for (int k = 0; k < PG; k++) {
        int n = g_selidx[k];
        float w = g_selw[k];
        float4 v = ((const float4*)(g_framepool + ((size_t)n * NQ + g) * DD))[d4];
        acc.x = fmaf(w, v.x, acc.x);
        acc.y = fmaf(w, v.y, acc.y);
        acc.z = fmaf(w, v.z, acc.z);
        acc.w = fmaf(w, v.w, acc.w);
    }
    float sc = g_scale;
    acc.x *= sc; acc.y *= sc; acc.z *= sc; acc.w *= sc;
    ((float4*)(g_pooled + g * DD))[d4] = acc;
}

// ---------------------------------------------------------------------------
// launch
// ---------------------------------------------------------------------------
extern "C" void kernel_launch(void* const* d_in, const int* in_sizes, int n_in,
                              void* d_out, int out_size) {
    const float* vf    = (const float*)d_in[0];
    const float* gu    = (const float*)d_in[1];
    const float* W_agg = (const float*)d_in[2];
    const float* b_agg = (const float*)d_in[3];
    const float* ln_g  = (const float*)d_in[4];
    const float* ln_b  = (const float*)d_in[5];
    const float* W1    = (const float*)d_in[6];
    const float* b1    = (const float*)d_in[7];
    const float* W2    = (const float*)d_in[8];
    const float* b2    = (const float*)d_in[9];
    const float* W_th  = (const float*)d_in[10];
    const float* b_th  = (const float*)d_in[11];
    float* out = (float*)d_out;

    float* d_part;   cudaGetSymbolAddress((void**)&d_part,   g_part);
    float* d_mom;    cudaGetSymbolAddress((void**)&d_mom,    g_mommean);
    float* d_feat;   cudaGetSymbolAddress((void**)&d_feat,   g_feat);
    float* d_xn;     cudaGetSymbolAddress((void**)&d_xn,     g_xn);
    float* d_h;      cudaGetSymbolAddress((void**)&d_h,      g_h);
    float* d_pooled; cudaGetSymbolAddress((void**)&d_pooled, g_pooled);

    // 1) stream video features once
    pool_kernel<<<dim3(NQ, NF), 384>>>(vf);
    // 2) frame means
    mean_kernel<<<NF, 384>>>();
    // 3) momentum EMA scan
    scan_kernel<<<4, 384>>>();
    // 4) feat = mommean @ W_agg + b_agg   (split-K=4)
    gemm_splitk<<<dim3(DD / BN, (NM1 + BM - 1) / BM, 4), 256>>>(d_mom, W_agg, d_part, NM1, DD, DD);
    combine_kernel<<<(NM1 * DD + 255) / 256, 256>>>(d_part, b_agg, d_feat, NM1, DD, 4, 0);
    // 5) LayerNorm
    ln_kernel<<<NM1, 256>>>(ln_g, ln_b);
    // 6) h = gelu(xn @ W1 + b1)
    gemm_splitk<<<dim3(DD / BN, (NM1 + BM - 1) / BM, 4), 256>>>(d_xn, W1, d_part, NM1, DD, DD);
    combine_kernel<<<(NM1 * DD + 255) / 256, 256>>>(d_part, b1, d_h, NM1, DD, 4, 1);
    // 7) gate logits + gumbel softmax y
    gate_kernel<<<NM1, 64>>>(W2, b2, gu, out);
    // 8) top-8 + z_hard
    topk_kernel<<<1, 128>>>(out);
    // 9) pooled from framepool (selected frames only)
    pooled_kernel<<<NQ, 384>>>();
    // 10) thumbnail = pooled @ W_th + b_th
    gemm_splitk<<<dim3(LM / BN, NQ / BM, 4), 256>>>(d_pooled, W_th, d_part, NQ, LM, DD);
    combine_kernel<<<(NQ * LM + 255) / 256, 256>>>(d_part, b_th, out + OUT_TH, NQ, LM, 4, 0);
}

// round 11
// speedup vs baseline: 1.0266x; 1.0266x over previous
#include <cuda_runtime.h>
#include <cuda_bf16.h>
#include <math.h>

// ---------------------------------------------------------------------------
// Problem constants
// ---------------------------------------------------------------------------
#define NF   128          // frames
#define PP   576          // patches
#define DD   1536         // feature dim
#define LM   4096
#define NQ   64
#define PG   9            // patches per pool group (576/64)
#define NM1  127          // N-1
#define NCUBES 8
#define SPLITK 8

#define OUT_GATE 0
#define OUT_TH   254
#define OUT_Z    (254 + NQ * LM)   // 262398

// ---------------------------------------------------------------------------
// Scratch (static __device__ arrays; no allocation)
// ---------------------------------------------------------------------------
__device__ float g_framemean[NF * DD];
__device__ float g_mommean[NF * DD];                  // rows 0..126 used
__device__ float g_feat[NF * DD];
__device__ float g_xn[NF * DD];
__device__ float g_h[NF * DD];
__device__ float g_pooled[NQ * DD];
__device__ float g_part[SPLITK * NQ * LM];            // split-K partials (8 MB)
__device__ float g_y[NM1];
__device__ int   g_selidx[PG];
__device__ float g_selw[PG];
__device__ float g_scale;

// ---------------------------------------------------------------------------
// K1: one streaming pass over video_features -> framemean[n][d]
// grid (128 frames, 3 d-chunks of 128 float4), 256 threads.
// Two thread-halves each sum 288 patches, combined via smem.
// ---------------------------------------------------------------------------
__global__ void __launch_bounds__(256) framesum_kernel(const float* __restrict__ vf) {
    int n = blockIdx.x;
    int col = blockIdx.y * 128 + (threadIdx.x & 127);   // float4 column 0..383
    int half = threadIdx.x >> 7;                         // 0 or 1
    const float4* base = (const float4*)(vf + (size_t)n * PP * DD) + col;
    float4 s = make_float4(0.f, 0.f, 0.f, 0.f);
#pragma unroll 4
    for (int p = half; p < PP; p += 2) {
        float4 v = base[(size_t)p * (DD / 4)];
        s.x += v.x; s.y += v.y; s.z += v.z; s.w += v.w;
    }
    __shared__ float4 sh[128];
    if (half == 1) sh[threadIdx.x & 127] = s;
    __syncthreads();
    if (half == 0) {
        float4 o = sh[threadIdx.x];
        const float inv = 1.0f / (float)PP;
        s.x = (s.x + o.x) * inv;
        s.y = (s.y + o.y) * inv;
        s.z = (s.z + o.z) * inv;
        s.w = (s.w + o.w) * inv;
        ((float4*)(g_framemean + n * DD))[col] = s;
    }
}

// ---------------------------------------------------------------------------
// K2: momentum EMA scan over frame-diffs of framemean
// ---------------------------------------------------------------------------
__global__ void scan_kernel() {
    int d = blockIdx.x * blockDim.x + threadIdx.x;
    if (d >= DD) return;
    float fm_prev = g_framemean[d];
    float fm_cur  = g_framemean[DD + d];
    float m = fm_cur - fm_prev;
    g_mommean[d] = m;
#pragma unroll 4
    for (int i = 1; i < NM1; i++) {
        fm_prev = fm_cur;
        fm_cur = g_framemean[(i + 1) * DD + d];
        float diff = fm_cur - fm_prev;
        m = 0.5f * diff + 0.5f * m;
        g_mommean[i * DD + d] = m;
    }
}

// ---------------------------------------------------------------------------
// Split-K fp32 GEMM, double-buffered smem: part[z] = A[M,Kchunk] @ B[Kchunk,N]
// BM=32, BN=128, BK=32, 256 threads, 4x4 microtile, deterministic partials.
// ---------------------------------------------------------------------------
#define BM 32
#define BN 128
#define BK 32
__global__ void __launch_bounds__(256) gemm_splitk(
    const float* __restrict__ A, const float* __restrict__ B,
    float* __restrict__ Cpart, int M, int N, int K)
{
    __shared__ float As[2][BK][BM];
    __shared__ float Bs[2][BK][BN];
    int tid = threadIdx.x;
    int n0 = blockIdx.x * BN;
    int m0 = blockIdx.y * BM;
    int splitk = gridDim.z;
    int kchunk = K / splitk;
    int k0 = blockIdx.z * kchunk;
    int ksteps = kchunk / BK;

    int ty = tid >> 5;            // warp id -> rows ty*4..ty*4+3
    int tx = tid & 31;            // lane    -> cols tx*4..tx*4+3
    int a_m = tid >> 3;           // 0..31
    int a_k = (tid & 7) * 4;      // 0..28
    int b_r = tid >> 5;           // 0..7
    int b_c = (tid & 31) * 4;     // 0..124

    float acc[4][4] = {};
    float4 a_reg;
    float4 b_reg[4];

    int mg = m0 + a_m;
    const float* Arow = A + (size_t)mg * K;
    bool a_ok = (mg < M);

    // prefetch tile 0 -> regs -> smem[0]
    {
        int kbase = k0;
        a_reg = a_ok ? *(const float4*)&Arow[kbase + a_k]
                     : make_float4(0.f, 0.f, 0.f, 0.f);
#pragma unroll
        for (int j = 0; j < 4; j++)
            b_reg[j] = *(const float4*)&B[(size_t)(kbase + b_r + j * 8) * N + n0 + b_c];
    }
    As[0][a_k + 0][a_m] = a_reg.x;
    As[0][a_k + 1][a_m] = a_reg.y;
    As[0][a_k + 2][a_m] = a_reg.z;
    As[0][a_k + 3][a_m] = a_reg.w;
#pragma unroll
    for (int j = 0; j < 4; j++)
        *(float4*)&Bs[0][b_r + j * 8][b_c] = b_reg[j];
    __syncthreads();

    for (int kt = 0; kt < ksteps; kt++) {
        int cur = kt & 1;
        if (kt + 1 < ksteps) {
            int kbase = k0 + (kt + 1) * BK;
            a_reg = a_ok ? *(const float4*)&Arow[kbase + a_k]
                         : make_float4(0.f, 0.f, 0.f, 0.f);
#pragma unroll
            for (int j = 0; j < 4; j++)
                b_reg[j] = *(const float4*)&B[(size_t)(kbase + b_r + j * 8) * N + n0 + b_c];
        }
#pragma unroll
        for (int kk = 0; kk < BK; kk++) {
            float4 a = *(const float4*)&As[cur][kk][ty * 4];
            float4 b = *(const float4*)&Bs[cur][kk][tx * 4];
            float ar[4] = {a.x, a.y, a.z, a.w};
            float br[4] = {b.x, b.y, b.z, b.w};
#pragma unroll
            for (int i = 0; i < 4; i++)
#pragma unroll
                for (int j = 0; j < 4; j++)
                    acc[i][j] = fmaf(ar[i], br[j], acc[i][j]);
        }
        if (kt + 1 < ksteps) {
            int nxt = cur ^ 1;
            As[nxt][a_k + 0][a_m] = a_reg.x;
            As[nxt][a_k + 1][a_m] = a_reg.y;
            As[nxt][a_k + 2][a_m] = a_reg.z;
            As[nxt][a_k + 3][a_m] = a_reg.w;
#pragma unroll
            for (int j = 0; j < 4; j++)
                *(float4*)&Bs[nxt][b_r + j * 8][b_c] = b_reg[j];
            __syncthreads();
        }
    }

    size_t MN = (size_t)M * N;
    float* base = Cpart + (size_t)blockIdx.z * MN;
#pragma unroll
    for (int i = 0; i < 4; i++) {
        int mo = m0 + ty * 4 + i;
        if (mo < M) {
            float4 v = make_float4(acc[i][0], acc[i][1], acc[i][2], acc[i][3]);
            *(float4*)&base[(size_t)mo * N + n0 + tx * 4] = v;
        }
    }
}

// ---------------------------------------------------------------------------
// Combine split-K partials + bias (+ optional exact GELU)
// ---------------------------------------------------------------------------
__global__ void combine_kernel(const float* __restrict__ part,
                               const float* __restrict__ bias,
                               float* __restrict__ dst,
                               int M, int N, int splitk, int do_gelu)
{
    int idx = blockIdx.x * blockDim.x + threadIdx.x;
    int total = M * N;
    if (idx >= total) return;
    float v = bias[idx % N];
    size_t MN = (size_t)total;
#pragma unroll 8
    for (int z = 0; z < splitk; z++) v += part[(size_t)z * MN + idx];
    if (do_gelu) v = 0.5f * v * (1.0f + erff(v * 0.70710678118654752f));
    dst[idx] = v;
}

// ---------------------------------------------------------------------------
// LayerNorm over feat rows -> xn
// ---------------------------------------------------------------------------
__global__ void __launch_bounds__(256) ln_kernel(const float* __restrict__ ln_g,
                                                 const float* __restrict__ ln_b)
{
    int row = blockIdx.x;
    const float* x = g_feat + row * DD;
    float s = 0.f, ss = 0.f;
    for (int d = threadIdx.x; d < DD; d += 256) {
        float v = x[d];
        s += v;
        ss = fmaf(v, v, ss);
    }
    __shared__ float sh1[8], sh2[8];
    int lane = threadIdx.x & 31, w = threadIdx.x >> 5;
#pragma unroll
    for (int o = 16; o; o >>= 1) {
        s  += __shfl_xor_sync(0xFFFFFFFFu, s, o);
        ss += __shfl_xor_sync(0xFFFFFFFFu, ss, o);
    }
    if (lane == 0) { sh1[w] = s; sh2[w] = ss; }
    __syncthreads();
    if (w == 0) {
        s  = (lane < 8) ? sh1[lane] : 0.f;
        ss = (lane < 8) ? sh2[lane] : 0.f;
#pragma unroll
        for (int o = 4; o; o >>= 1) {
            s  += __shfl_xor_sync(0xFFFFFFFFu, s, o);
            ss += __shfl_xor_sync(0xFFFFFFFFu, ss, o);
        }
        if (lane == 0) { sh1[0] = s; sh2[0] = ss; }
    }
    __syncthreads();
    float mu  = sh1[0] * (1.0f / DD);
    float var = sh2[0] * (1.0f / DD) - mu * mu;
    float rstd = rsqrtf(var + 1e-5f);
    for (int d = threadIdx.x; d < DD; d += 256)
        g_xn[row * DD + d] = (x[d] - mu) * rstd * ln_g[d] + ln_b[d];
}

// ---------------------------------------------------------------------------
// Gate head: gate_logits = h @ W2 + b2 ; y = softmax((logits + g*0.1)/0.5)[1]
// ---------------------------------------------------------------------------
__global__ void __launch_bounds__(64) gate_kernel(const float* __restrict__ W2,
                                                  const float* __restrict__ b2,
                                                  const float* __restrict__ gu,
                                                  float* __restrict__ out)
{
    int row = blockIdx.x;
    int w = threadIdx.x >> 5, lane = threadIdx.x & 31;
    const float* hrow = g_h + row * DD;
    float s = 0.f;
    for (int d = lane; d < DD; d += 32)
        s = fmaf(hrow[d], W2[d * 2 + w], s);
#pragma unroll
    for (int o = 16; o; o >>= 1) s += __shfl_xor_sync(0xFFFFFFFFu, s, o);
    __shared__ float sl[2];
    if (lane == 0) sl[w] = s + b2[w];
    __syncthreads();
    if (threadIdx.x == 0) {
        float l0 = sl[0], l1 = sl[1];
        out[OUT_GATE + row * 2 + 0] = l0;
        out[OUT_GATE + row * 2 + 1] = l1;
        float u0 = gu[row * 2 + 0], u1 = gu[row * 2 + 1];
        float g0 = -logf(-logf(u0 + 1e-20f) + 1e-20f);
        float g1 = -logf(-logf(u1 + 1e-20f) + 1e-20f);
        float a0 = (l0 + g0 * 0.1f) * 2.0f;   // / TEMP(0.5)
        float a1 = (l1 + g1 * 0.1f) * 2.0f;
        float mx = fmaxf(a0, a1);
        float e0 = expf(a0 - mx), e1 = expf(a1 - mx);
        g_y[row] = e1 / (e0 + e1);
    }
}

// ---------------------------------------------------------------------------
// Top-8 selection (stable: max value, lowest index on ties), z_hard, weights
// ---------------------------------------------------------------------------
__global__ void __launch_bounds__(128) topk_kernel(float* __restrict__ out) {
    __shared__ float yv[128];
    __shared__ float rv[128];
    __shared__ int   ri[128];
    __shared__ int   taken[128];
    int t = threadIdx.x;
    yv[t] = (t < NM1) ? g_y[t] : -1e30f;
    taken[t] = 0;
    __syncthreads();
    for (int it = 0; it < NCUBES; it++) {
        rv[t] = taken[t] ? -1e30f : yv[t];
        ri[t] = t;
        __syncthreads();
        for (int off = 64; off > 0; off >>= 1) {
            if (t < off) {
                float v2 = rv[t + off]; int i2 = ri[t + off];
                if (v2 > rv[t] || (v2 == rv[t] && i2 < ri[t])) { rv[t] = v2; ri[t] = i2; }
            }
            __syncthreads();
        }
        if (t == 0) taken[ri[0]] = 1;
        __syncthreads();
    }
    float z = 0.f;
    if (t < NM1) z = taken[t] ? ((1.0f - yv[t]) + yv[t]) : 0.0f;
    if (t == 0) out[OUT_Z] = 1.0f;
    if (t < NM1) out[OUT_Z + 1 + t] = z;
    rv[t] = z;
    __syncthreads();
    for (int off = 64; off > 0; off >>= 1) {
        if (t < off) rv[t] += rv[t + off];
        __syncthreads();
    }
    if (t == 0) {
        float zsum = 1.0f + rv[0];
        g_scale = 1.0f / ((float)PG * zsum);
        g_selidx[0] = 0; g_selw[0] = 1.0f;
        int c = 1;
        for (int i = 0; i < NM1; i++) {
            if (taken[i]) {
                g_selidx[c] = i + 1;
                g_selw[c] = (1.0f - yv[i]) + yv[i];
                c++;
            }
        }
    }
}

// ---------------------------------------------------------------------------
// pooled[g][d] = scale * sum_k w_k * sum_{p in group g} vf[sel_k][p][d]
// Reads 9 selected frames directly from vf (~32 MB).
// grid (64 groups, 3 chunks), 128 threads (float4 each).
// ---------------------------------------------------------------------------
__global__ void __launch_bounds__(128) pooled_kernel(const float* __restrict__ vf) {
    int g = blockIdx.x;
    int d4 = blockIdx.y * 128 + threadIdx.x;   // 0..383
    float4 acc = make_float4(0.f, 0.f, 0.f, 0.f);
#pragma unroll
    for (int k = 0; k < PG; k++) {
        int n = g_selidx[k];
        float w = g_selw[k];
        const float4* base =
            (const float4*)(vf + ((size_t)n * PP + (size_t)g * PG) * DD) + d4;
#pragma unroll
        for (int r = 0; r < PG; r++) {
            float4 v = base[(size_t)r * (DD / 4)];
            acc.x = fmaf(w, v.x, acc.x);
            acc.y = fmaf(w, v.y, acc.y);
            acc.z = fmaf(w, v.z, acc.z);
            acc.w = fmaf(w, v.w, acc.w);
        }
    }
    float sc = g_scale;
    acc.x *= sc; acc.y *= sc; acc.z *= sc; acc.w *= sc;
    ((float4*)(g_pooled + g * DD))[d4] = acc;
}

// ---------------------------------------------------------------------------
// launch
// ---------------------------------------------------------------------------
extern "C" void kernel_launch(void* const* d_in, const int* in_sizes, int n_in,
                              void* d_out, int out_size) {
    const float* vf    = (const float*)d_in[0];
    const float* gu    = (const float*)d_in[1];
    const float* W_agg = (const float*)d_in[2];
    const float* b_agg = (const float*)d_in[3];
    const float* ln_g  = (const float*)d_in[4];
    const float* ln_b  = (const float*)d_in[5];
    const float* W1    = (const float*)d_in[6];
    const float* b1    = (const float*)d_in[7];
    const float* W2    = (const float*)d_in[8];
    const float* b2    = (const float*)d_in[9];
    const float* W_th  = (const float*)d_in[10];
    const float* b_th  = (const float*)d_in[11];
    float* out = (float*)d_out;

    float* d_part;   cudaGetSymbolAddress((void**)&d_part,   g_part);
    float* d_mom;    cudaGetSymbolAddress((void**)&d_mom,    g_mommean);
    float* d_feat;   cudaGetSymbolAddress((void**)&d_feat,   g_feat);
    float* d_xn;     cudaGetSymbolAddress((void**)&d_xn,     g_xn);
    float* d_h;      cudaGetSymbolAddress((void**)&d_h,      g_h);
    float* d_pooled; cudaGetSymbolAddress((void**)&d_pooled, g_pooled);

    // 1) stream video features once -> framemean
    framesum_kernel<<<dim3(NF, 3), 256>>>(vf);
    // 2) momentum EMA scan
    scan_kernel<<<4, 384>>>();
    // 3) feat = mommean @ W_agg + b_agg   (split-K=8)
    gemm_splitk<<<dim3(DD / BN, (NM1 + BM - 1) / BM, SPLITK), 256>>>(d_mom, W_agg, d_part, NM1, DD, DD);
    combine_kernel<<<(NM1 * DD + 255) / 256, 256>>>(d_part, b_agg, d_feat, NM1, DD, SPLITK, 0);
    // 4) LayerNorm
    ln_kernel<<<NM1, 256>>>(ln_g, ln_b);
    // 5) h = gelu(xn @ W1 + b1)
    gemm_splitk<<<dim3(DD / BN, (NM1 + BM - 1) / BM, SPLITK), 256>>>(d_xn, W1, d_part, NM1, DD, DD);
    combine_kernel<<<(NM1 * DD + 255) / 256, 256>>>(d_part, b1, d_h, NM1, DD, SPLITK, 1);
    // 6) gate logits + gumbel softmax y
    gate_kernel<<<NM1, 64>>>(W2, b2, gu, out);
    // 7) top-8 + z_hard
    topk_kernel<<<1, 128>>>(out);
    // 8) pooled from selected frames (direct vf gather)
    pooled_kernel<<<dim3(NQ, 3), 128>>>(vf);
    // 9) thumbnail = pooled @ W_th + b_th
    gemm_splitk<<<dim3(LM / BN, NQ / BM, SPLITK), 256>>>(d_pooled, W_th, d_part, NQ, LM, DD);
    combine_kernel<<<(NQ * LM + 255) / 256, 256>>>(d_part, b_th, out + OUT_TH, NQ, LM, SPLITK, 0);
}

// round 12
// speedup vs baseline: 1.2079x; 1.1766x over previous
#include <cuda_runtime.h>
#include <cuda_bf16.h>
#include <math.h>
#include <stdint.h>

// ---------------------------------------------------------------------------
// Problem constants
// ---------------------------------------------------------------------------
#define NF   128          // frames
#define PP   576          // patches
#define DD   1536         // feature dim
#define LM   4096
#define NQ   64
#define PG   9            // patches per pool group (576/64)
#define NM1  127          // N-1
#define NCUBES 8
#define SPLITK 8

#define OUT_GATE 0
#define OUT_TH   254
#define OUT_Z    (254 + NQ * LM)   // 262398

// ---------------------------------------------------------------------------
// Scratch (static __device__ arrays; no allocation)
// ---------------------------------------------------------------------------
__device__ float g_framemean[NF * DD];
__device__ float g_mommean[NF * DD];                  // rows 0..126 used
__device__ float g_xn[NF * DD];
__device__ float g_pooled[NQ * DD];
__device__ float g_part[SPLITK * NQ * LM];            // split-K partials (8 MB)
__device__ float g_y[NM1];
__device__ int   g_selidx[PG];
__device__ float g_selw[PG];
__device__ float g_scale;

// ---------------------------------------------------------------------------
// tf32 helpers
// ---------------------------------------------------------------------------
__device__ __forceinline__ float f2tf32(float x) {
    uint32_t u;
    asm("cvt.rna.tf32.f32 %0, %1;" : "=r"(u) : "f"(x));
    return __uint_as_float(u);
}

#define MMA_TF32(dreg, a, b0, b1)                                              \
    asm volatile(                                                              \
        "mma.sync.aligned.m16n8k8.row.col.f32.tf32.tf32.f32 "                  \
        "{%0,%1,%2,%3}, {%4,%5,%6,%7}, {%8,%9}, {%0,%1,%2,%3};"                \
        : "+f"(dreg[0]), "+f"(dreg[1]), "+f"(dreg[2]), "+f"(dreg[3])           \
        : "r"(a[0]), "r"(a[1]), "r"(a[2]), "r"(a[3]), "r"(b0), "r"(b1))

// ---------------------------------------------------------------------------
// K1: one streaming pass over video_features -> framemean[n][d]
// ---------------------------------------------------------------------------
__global__ void __launch_bounds__(256) framesum_kernel(const float* __restrict__ vf) {
    int n = blockIdx.x;
    int col = blockIdx.y * 128 + (threadIdx.x & 127);   // float4 column 0..383
    int half = threadIdx.x >> 7;                         // 0 or 1
    const float4* base = (const float4*)(vf + (size_t)n * PP * DD) + col;
    float4 s = make_float4(0.f, 0.f, 0.f, 0.f);
#pragma unroll 8
    for (int p = half; p < PP; p += 2) {
        float4 v = base[(size_t)p * (DD / 4)];
        s.x += v.x; s.y += v.y; s.z += v.z; s.w += v.w;
    }
    __shared__ float4 sh[128];
    if (half == 1) sh[threadIdx.x & 127] = s;
    __syncthreads();
    if (half == 0) {
        float4 o = sh[threadIdx.x];
        const float inv = 1.0f / (float)PP;
        s.x = (s.x + o.x) * inv;
        s.y = (s.y + o.y) * inv;
        s.z = (s.z + o.z) * inv;
        s.w = (s.w + o.w) * inv;
        ((float4*)(g_framemean + n * DD))[col] = s;
    }
}

// ---------------------------------------------------------------------------
// K2: windowed-parallel momentum EMA scan.
// mom[0]=diff[0]; mom[i]=0.5*diff[i]+0.5*mom[i-1]
//   => mom[i] = 0.5^i diff[0] + sum_{j=1..i} 0.5^{i-j+1} diff[j]
// Truncate weights below 0.5^40 (~9e-13): each block seeds m at row s-1 via a
// 40-term window, then does 8 sequential steps. grid(16), 384 threads (float4).
// ---------------------------------------------------------------------------
#define SCAN_SEG 8
#define SCAN_WIN 40
__global__ void __launch_bounds__(384) scan_kernel() {
    int b = blockIdx.x;
    int s = b * SCAN_SEG;
    int c4 = threadIdx.x;                     // float4 col 0..383
    const float4* fm = (const float4*)g_framemean;
    float4* mom = (float4*)g_mommean;

    float4 m;
    int istart;
    if (b == 0) {
        float4 f0 = fm[c4];
        float4 f1 = fm[384 + c4];
        m = make_float4(f1.x - f0.x, f1.y - f0.y, f1.z - f0.z, f1.w - f0.w);
        mom[c4] = m;
        istart = 1;
    } else {
        int istar = s - 1;
        int jlo = istar - (SCAN_WIN - 1); if (jlo < 0) jlo = 0;
        float w = 0.5f;
        float4 acc = make_float4(0.f, 0.f, 0.f, 0.f);
        for (int j = istar; j >= jlo; j--) {
            float4 fa = fm[(size_t)j * 384 + c4];
            float4 fb = fm[(size_t)(j + 1) * 384 + c4];
            acc.x = fmaf(w, fb.x - fa.x, acc.x);
            acc.y = fmaf(w, fb.y - fa.y, acc.y);
            acc.z = fmaf(w, fb.z - fa.z, acc.z);
            acc.w = fmaf(w, fb.w - fa.w, acc.w);
            if (j >= 2) w *= 0.5f;            // diff[0] shares diff[1]'s weight
        }
        m = acc;
        istart = s;
    }
#pragma unroll
    for (int i0 = 0; i0 < SCAN_SEG; i0++) {
        int i = (b == 0) ? (istart + i0) : (s + i0);
        if (i >= NM1) break;
        if (b == 0 && i0 >= SCAN_SEG - 1 && istart + i0 >= SCAN_SEG) break;
        if (i < istart) continue;
        float4 fa = fm[(size_t)i * 384 + c4];
        float4 fb = fm[(size_t)(i + 1) * 384 + c4];
        m.x = 0.5f * (fb.x - fa.x) + 0.5f * m.x;
        m.y = 0.5f * (fb.y - fa.y) + 0.5f * m.y;
        m.z = 0.5f * (fb.z - fa.z) + 0.5f * m.z;
        m.w = 0.5f * (fb.w - fa.w) + 0.5f * m.w;
        mom[(size_t)i * 384 + c4] = m;
    }
}

// ---------------------------------------------------------------------------
// tf32 tensor-core split-K GEMM with hi/lo error compensation.
// Cpart[z] = A[M, Kchunk_z] @ B[Kchunk_z, N]
// BM=64, BN=64, BK=16, 256 threads (8 warps: 4 m-warps x 2 n-warps),
// each warp: 16x32 output via 4 n8 mma tiles, 3 mma per tile (hh, hl, lh).
// ---------------------------------------------------------------------------
#define GBM 64
#define GBN 64
#define GBK 16
#define ASTR (GBK + 4)    // 20 words: conflict-free a-frag rows, 16B aligned
#define BSTR (GBN + 4)    // 68 words: conflict-free b-frag rows, 16B aligned

__global__ void __launch_bounds__(256) gemm_tf32_splitk(
    const float* __restrict__ A, const float* __restrict__ B,
    float* __restrict__ Cpart, int M, int N, int K)
{
    __shared__ float As_hi[2][GBM][ASTR];
    __shared__ float As_lo[2][GBM][ASTR];
    __shared__ float Bs_hi[2][GBK][BSTR];
    __shared__ float Bs_lo[2][GBK][BSTR];

    int tid = threadIdx.x;
    int lane = tid & 31, wid = tid >> 5;
    int wm = (wid & 3) * 16;
    int wn = (wid >> 2) * 32;
    int g = lane >> 2, t = lane & 3;

    int n0 = blockIdx.x * GBN;
    int m0 = blockIdx.y * GBM;
    int kchunk = K / gridDim.z;
    int k0 = blockIdx.z * kchunk;
    int ksteps = kchunk / GBK;

    // tile-load mapping
    int ar = tid >> 2;              // 0..63
    int ac = (tid & 3) * 4;         // 0,4,8,12
    int br = tid >> 4;              // 0..15
    int bc = (tid & 15) * 4;        // 0..60

    bool a_ok = (m0 + ar) < M;
    const float* Aptr = A + (size_t)(m0 + ar) * K + k0 + ac;
    const float* Bptr = B + (size_t)(k0 + br) * N + n0 + bc;

    float d[4][4];
#pragma unroll
    for (int j = 0; j < 4; j++)
#pragma unroll
        for (int i = 0; i < 4; i++) d[j][i] = 0.f;

    float4 a_pre = a_ok ? *(const float4*)Aptr : make_float4(0.f, 0.f, 0.f, 0.f);
    float4 b_pre = *(const float4*)Bptr;

    auto stage = [&](int buf, float4 av, float4 bv) {
        float h0 = f2tf32(av.x), h1 = f2tf32(av.y), h2 = f2tf32(av.z), h3 = f2tf32(av.w);
        *(float4*)&As_hi[buf][ar][ac] = make_float4(h0, h1, h2, h3);
        *(float4*)&As_lo[buf][ar][ac] =
            make_float4(f2tf32(av.x - h0), f2tf32(av.y - h1),
                        f2tf32(av.z - h2), f2tf32(av.w - h3));
        float p0 = f2tf32(bv.x), p1 = f2tf32(bv.y), p2 = f2tf32(bv.z), p3 = f2tf32(bv.w);
        *(float4*)&Bs_hi[buf][br][bc] = make_float4(p0, p1, p2, p3);
        *(float4*)&Bs_lo[buf][br][bc] =
            make_float4(f2tf32(bv.x - p0), f2tf32(bv.y - p1),
                        f2tf32(bv.z - p2), f2tf32(bv.w - p3));
    };

    stage(0, a_pre, b_pre);
    __syncthreads();

    for (int kt = 0; kt < ksteps; kt++) {
        int cur = kt & 1;
        if (kt + 1 < ksteps) {
            a_pre = a_ok ? *(const float4*)(Aptr + (kt + 1) * GBK)
                         : make_float4(0.f, 0.f, 0.f, 0.f);
            b_pre = *(const float4*)(Bptr + (size_t)(kt + 1) * GBK * N);
        }
#pragma unroll
        for (int ks = 0; ks < 2; ks++) {
            int kk = ks * 8;
            uint32_t ah[4], al[4];
            ah[0] = __float_as_uint(As_hi[cur][wm + g    ][kk + t    ]);
            ah[1] = __float_as_uint(As_hi[cur][wm + g + 8][kk + t    ]);
            ah[2] = __float_as_uint(As_hi[cur][wm + g    ][kk + t + 4]);
            ah[3] = __float_as_uint(As_hi[cur][wm + g + 8][kk + t + 4]);
            al[0] = __float_as_uint(As_lo[cur][wm + g    ][kk + t    ]);
            al[1] = __float_as_uint(As_lo[cur][wm + g + 8][kk + t    ]);
            al[2] = __float_as_uint(As_lo[cur][wm + g    ][kk + t + 4]);
            al[3] = __float_as_uint(As_lo[cur][wm + g + 8][kk + t + 4]);
#pragma unroll
            for (int j = 0; j < 4; j++) {
                int n = wn + j * 8 + g;
                uint32_t bh0 = __float_as_uint(Bs_hi[cur][kk + t    ][n]);
                uint32_t bh1 = __float_as_uint(Bs_hi[cur][kk + t + 4][n]);
                uint32_t bl0 = __float_as_uint(Bs_lo[cur][kk + t    ][n]);
                uint32_t bl1 = __float_as_uint(Bs_lo[cur][kk + t + 4][n]);
                MMA_TF32(d[j], ah, bh0, bh1);   // hi*hi
                MMA_TF32(d[j], ah, bl0, bl1);   // hi*lo
                MMA_TF32(d[j], al, bh0, bh1);   // lo*hi
            }
        }
        if (kt + 1 < ksteps) {
            stage(cur ^ 1, a_pre, b_pre);
            __syncthreads();
        }
    }

    size_t MN = (size_t)M * N;
    float* Cb = Cpart + (size_t)blockIdx.z * MN;
#pragma unroll
    for (int j = 0; j < 4; j++) {
        int col = n0 + wn + j * 8 + 2 * t;
        int r0 = m0 + wm + g;
        if (r0 < M) *(float2*)&Cb[(size_t)r0 * N + col] = make_float2(d[j][0], d[j][1]);
        int r1 = r0 + 8;
        if (r1 < M) *(float2*)&Cb[(size_t)r1 * N + col] = make_float2(d[j][2], d[j][3]);
    }
}

// ---------------------------------------------------------------------------
// Fused: combine split-K partials (+b_agg) -> LayerNorm -> g_xn. One row/block.
// ---------------------------------------------------------------------------
__global__ void __launch_bounds__(256) ln_combine_kernel(
    const float* __restrict__ part, const float* __restrict__ b_agg,
    const float* __restrict__ ln_g, const float* __restrict__ ln_b)
{
    int row = blockIdx.x;
    const size_t MN = (size_t)NM1 * DD;
    const float* base = part + (size_t)row * DD;
    float v[6];
    float s = 0.f, ss = 0.f;
#pragma unroll
    for (int c = 0; c < 6; c++) {
        int col = threadIdx.x + c * 256;
        float a = b_agg[col];
#pragma unroll
        for (int z = 0; z < SPLITK; z++) a += base[(size_t)z * MN + col];
        v[c] = a;
        s += a;
        ss = fmaf(a, a, ss);
    }
    __shared__ float sh1[8], sh2[8];
    int lane = threadIdx.x & 31, w = threadIdx.x >> 5;
#pragma unroll
    for (int o = 16; o; o >>= 1) {
        s  += __shfl_xor_sync(0xFFFFFFFFu, s, o);
        ss += __shfl_xor_sync(0xFFFFFFFFu, ss, o);
    }
    if (lane == 0) { sh1[w] = s; sh2[w] = ss; }
    __syncthreads();
    if (w == 0) {
        s  = (lane < 8) ? sh1[lane] : 0.f;
        ss = (lane < 8) ? sh2[lane] : 0.f;
#pragma unroll
        for (int o = 4; o; o >>= 1) {
            s  += __shfl_xor_sync(0xFFFFFFFFu, s, o);
            ss += __shfl_xor_sync(0xFFFFFFFFu, ss, o);
        }
        if (lane == 0) { sh1[0] = s; sh2[0] = ss; }
    }
    __syncthreads();
    float mu  = sh1[0] * (1.0f / DD);
    float var = sh2[0] * (1.0f / DD) - mu * mu;
    float rstd = rsqrtf(var + 1e-5f);
#pragma unroll
    for (int c = 0; c < 6; c++) {
        int col = threadIdx.x + c * 256;
        g_xn[row * DD + col] = (v[c] - mu) * rstd * ln_g[col] + ln_b[col];
    }
}

// ---------------------------------------------------------------------------
// Fused: combine split-K partials (+b1) -> GELU -> dot with W2 (+b2) ->
// gate logits (to out) + gumbel-softmax y (to g_y). One row/block.
// ---------------------------------------------------------------------------
__global__ void __launch_bounds__(256) gate_combine_kernel(
    const float* __restrict__ part, const float* __restrict__ b1,
    const float* __restrict__ W2, const float* __restrict__ b2,
    const float* __restrict__ gu, float* __restrict__ out)
{
    int row = blockIdx.x;
    const size_t MN = (size_t)NM1 * DD;
    const float* base = part + (size_t)row * DD;
    float s0 = 0.f, s1 = 0.f;
#pragma unroll
    for (int c = 0; c < 6; c++) {
        int col = threadIdx.x + c * 256;
        float a = b1[col];
#pragma unroll
        for (int z = 0; z < SPLITK; z++) a += base[(size_t)z * MN + col];
        a = 0.5f * a * (1.0f + erff(a * 0.70710678118654752f));   // exact GELU
        float2 w2 = *(const float2*)&W2[col * 2];
        s0 = fmaf(a, w2.x, s0);
        s1 = fmaf(a, w2.y, s1);
    }
    __shared__ float sh0[8], sh1w[8];
    int lane = threadIdx.x & 31, w = threadIdx.x >> 5;
#pragma unroll
    for (int o = 16; o; o >>= 1) {
        s0 += __shfl_xor_sync(0xFFFFFFFFu, s0, o);
        s1 += __shfl_xor_sync(0xFFFFFFFFu, s1, o);
    }
    if (lane == 0) { sh0[w] = s0; sh1w[w] = s1; }
    __syncthreads();
    if (threadIdx.x == 0) {
        float l0 = b2[0], l1 = b2[1];
#pragma unroll
        for (int i = 0; i < 8; i++) { l0 += sh0[i]; l1 += sh1w[i]; }
        out[OUT_GATE + row * 2 + 0] = l0;
        out[OUT_GATE + row * 2 + 1] = l1;
        float u0 = gu[row * 2 + 0], u1 = gu[row * 2 + 1];
        float g0 = -logf(-logf(u0 + 1e-20f) + 1e-20f);
        float g1 = -logf(-logf(u1 + 1e-20f) + 1e-20f);
        float a0 = (l0 + g0 * 0.1f) * 2.0f;   // / TEMP(0.5)
        float a1 = (l1 + g1 * 0.1f) * 2.0f;
        float mx = fmaxf(a0, a1);
        float e0 = expf(a0 - mx), e1 = expf(a1 - mx);
        g_y[row] = e1 / (e0 + e1);
    }
}

// ---------------------------------------------------------------------------
// Top-8 selection (stable: max value, lowest index on ties), z_hard, weights
// ---------------------------------------------------------------------------
__global__ void __launch_bounds__(128) topk_kernel(float* __restrict__ out) {
    __shared__ float yv[128];
    __shared__ float rv[128];
    __shared__ int   ri[128];
    __shared__ int   taken[128];
    int t = threadIdx.x;
    yv[t] = (t < NM1) ? g_y[t] : -1e30f;
    taken[t] = 0;
    __syncthreads();
    for (int it = 0; it < NCUBES; it++) {
        rv[t] = taken[t] ? -1e30f : yv[t];
        ri[t] = t;
        __syncthreads();
        for (int off = 64; off > 0; off >>= 1) {
            if (t < off) {
                float v2 = rv[t + off]; int i2 = ri[t + off];
                if (v2 > rv[t] || (v2 == rv[t] && i2 < ri[t])) { rv[t] = v2; ri[t] = i2; }
            }
            __syncthreads();
        }
        if (t == 0) taken[ri[0]] = 1;
        __syncthreads();
    }
    float z = 0.f;
    if (t < NM1) z = taken[t] ? ((1.0f - yv[t]) + yv[t]) : 0.0f;
    if (t == 0) out[OUT_Z] = 1.0f;
    if (t < NM1) out[OUT_Z + 1 + t] = z;
    rv[t] = z;
    __syncthreads();
    for (int off = 64; off > 0; off >>= 1) {
        if (t < off) rv[t] += rv[t + off];
        __syncthreads();
    }
    if (t == 0) {
        float zsum = 1.0f + rv[0];
        g_scale = 1.0f / ((float)PG * zsum);
        g_selidx[0] = 0; g_selw[0] = 1.0f;
        int c = 1;
        for (int i = 0; i < NM1; i++) {
            if (taken[i]) {
                g_selidx[c] = i + 1;
                g_selw[c] = (1.0f - yv[i]) + yv[i];
                c++;
            }
        }
    }
}

// ---------------------------------------------------------------------------
// pooled[g][d] = scale * sum_k w_k * sum_{p in group g} vf[sel_k][p][d]
// ---------------------------------------------------------------------------
__global__ void __launch_bounds__(128) pooled_kernel(const float* __restrict__ vf) {
    int g = blockIdx.x;
    int d4 = blockIdx.y * 128 + threadIdx.x;   // 0..383
    float4 acc = make_float4(0.f, 0.f, 0.f, 0.f);
#pragma unroll
    for (int k = 0; k < PG; k++) {
        int n = g_selidx[k];
        float w = g_selw[k];
        const float4* base =
            (const float4*)(vf + ((size_t)n * PP + (size_t)g * PG) * DD) + d4;
#pragma unroll
        for (int r = 0; r < PG; r++) {
            float4 v = base[(size_t)r * (DD / 4)];
            acc.x = fmaf(w, v.x, acc.x);
            acc.y = fmaf(w, v.y, acc.y);
            acc.z = fmaf(w, v.z, acc.z);
            acc.w = fmaf(w, v.w, acc.w);
        }
    }
    float sc = g_scale;
    acc.x *= sc; acc.y *= sc; acc.z *= sc; acc.w *= sc;
    ((float4*)(g_pooled + g * DD))[d4] = acc;
}

// ---------------------------------------------------------------------------
// Thumbnail combine: float2-vectorized (dst = out+254 is 8B aligned, not 16B)
// ---------------------------------------------------------------------------
__global__ void __launch_bounds__(256) combine_th_kernel(
    const float* __restrict__ part, const float* __restrict__ bias,
    float* __restrict__ dst)
{
    int idx = blockIdx.x * blockDim.x + threadIdx.x;   // float2 index
    const int total2 = NQ * LM / 2;
    if (idx >= total2) return;
    int col2 = idx & (LM / 2 - 1);
    float2 v = *(const float2*)&bias[col2 * 2];
    const float2* p2 = (const float2*)part;
#pragma unroll
    for (int z = 0; z < SPLITK; z++) {
        float2 a = p2[(size_t)z * total2 + idx];
        v.x += a.x; v.y += a.y;
    }
    *(float2*)&dst[idx * 2] = v;
}

// ---------------------------------------------------------------------------
// launch
// ---------------------------------------------------------------------------
extern "C" void kernel_launch(void* const* d_in, const int* in_sizes, int n_in,
                              void* d_out, int out_size) {
    const float* vf    = (const float*)d_in[0];
    const float* gu    = (const float*)d_in[1];
    const float* W_agg = (const float*)d_in[2];
    const float* b_agg = (const float*)d_in[3];
    const float* ln_g  = (const float*)d_in[4];
    const float* ln_b  = (const float*)d_in[5];
    const float* W1    = (const float*)d_in[6];
    const float* b1    = (const float*)d_in[7];
    const float* W2    = (const float*)d_in[8];
    const float* b2    = (const float*)d_in[9];
    const float* W_th  = (const float*)d_in[10];
    const float* b_th  = (const float*)d_in[11];
    float* out = (float*)d_out;

    float* d_part;   cudaGetSymbolAddress((void**)&d_part,   g_part);
    float* d_mom;    cudaGetSymbolAddress((void**)&d_mom,    g_mommean);
    float* d_xn;     cudaGetSymbolAddress((void**)&d_xn,     g_xn);
    float* d_pooled; cudaGetSymbolAddress((void**)&d_pooled, g_pooled);

    // 1) stream video features once -> framemean
    framesum_kernel<<<dim3(NF, 3), 256>>>(vf);
    // 2) windowed-parallel momentum EMA scan
    scan_kernel<<<16, 384>>>();
    // 3) feat partials = mommean @ W_agg   (tf32 TC, split-K=8)
    gemm_tf32_splitk<<<dim3(DD / GBN, 2, SPLITK), 256>>>(d_mom, W_agg, d_part, NM1, DD, DD);
    // 4) combine + bias + LayerNorm -> xn
    ln_combine_kernel<<<NM1, 256>>>(d_part, b_agg, ln_g, ln_b);
    // 5) h partials = xn @ W1
    gemm_tf32_splitk<<<dim3(DD / GBN, 2, SPLITK), 256>>>(d_xn, W1, d_part, NM1, DD, DD);
    // 6) combine + bias + GELU + gate head + gumbel y
    gate_combine_kernel<<<NM1, 256>>>(d_part, b1, W2, b2, gu, out);
    // 7) top-8 + z_hard
    topk_kernel<<<1, 128>>>(out);
    // 8) pooled from selected frames (direct vf gather)
    pooled_kernel<<<dim3(NQ, 3), 128>>>(vf);
    // 9) thumbnail partials = pooled @ W_th
    gemm_tf32_splitk<<<dim3(LM / GBN, 1, SPLITK), 256>>>(d_pooled, W_th, d_part, NQ, LM, DD);
    // 10) combine + bias -> out
    combine_th_kernel<<<(NQ * LM / 2 + 255) / 256, 256>>>(d_part, b_th, out + OUT_TH);
}

// round 13
// speedup vs baseline: 1.2223x; 1.0119x over previous
#include <cuda_runtime.h>
#include <cuda_bf16.h>
#include <math.h>
#include <stdint.h>

// ---------------------------------------------------------------------------
// Problem constants
// ---------------------------------------------------------------------------
#define NF   128          // frames
#define PP   576          // patches
#define DD   1536         // feature dim
#define LM   4096
#define NQ   64
#define PG   9            // patches per pool group (576/64)
#define NM1  127          // N-1
#define NCUBES 8
#define SPLITK 8          // for the two D x D GEMMs
#define SPLITK3 4         // for the thumbnail GEMM

#define OUT_GATE 0
#define OUT_TH   254
#define OUT_Z    (254 + NQ * LM)   // 262398

// ---------------------------------------------------------------------------
// Scratch (static __device__ arrays; no allocation)
// ---------------------------------------------------------------------------
__device__ float g_framemean[NF * DD];
__device__ float g_mommean[NF * DD];                  // rows 0..126 used
__device__ float g_xn[NF * DD];
__device__ float g_pooled[NQ * DD];
__device__ float g_part[SPLITK * NQ * LM];            // split-K partials (8 MB)
__device__ float g_y[NM1];
__device__ int   g_selidx[PG];
__device__ float g_selw[PG];
__device__ float g_scale;

// ---------------------------------------------------------------------------
// tf32 helpers
// ---------------------------------------------------------------------------
__device__ __forceinline__ float f2tf32(float x) {
    uint32_t u;
    asm("cvt.rna.tf32.f32 %0, %1;" : "=r"(u) : "f"(x));
    return __uint_as_float(u);
}

#define MMA_TF32(dreg, a, b0, b1)                                              \
    asm volatile(                                                              \
        "mma.sync.aligned.m16n8k8.row.col.f32.tf32.tf32.f32 "                  \
        "{%0,%1,%2,%3}, {%4,%5,%6,%7}, {%8,%9}, {%0,%1,%2,%3};"                \
        : "+f"(dreg[0]), "+f"(dreg[1]), "+f"(dreg[2]), "+f"(dreg[3])           \
        : "r"(a[0]), "r"(a[1]), "r"(a[2]), "r"(a[3]), "r"(b0), "r"(b1))

// ---------------------------------------------------------------------------
// K1: one streaming pass over video_features -> framemean[n][d]
// ---------------------------------------------------------------------------
__global__ void __launch_bounds__(256) framesum_kernel(const float* __restrict__ vf) {
    int n = blockIdx.x;
    int col = blockIdx.y * 128 + (threadIdx.x & 127);   // float4 column 0..383
    int half = threadIdx.x >> 7;                         // 0 or 1
    const float4* base = (const float4*)(vf + (size_t)n * PP * DD) + col;
    float4 s = make_float4(0.f, 0.f, 0.f, 0.f);
#pragma unroll 8
    for (int p = half; p < PP; p += 2) {
        float4 v = base[(size_t)p * (DD / 4)];
        s.x += v.x; s.y += v.y; s.z += v.z; s.w += v.w;
    }
    __shared__ float4 sh[128];
    if (half == 1) sh[threadIdx.x & 127] = s;
    __syncthreads();
    if (half == 0) {
        float4 o = sh[threadIdx.x];
        const float inv = 1.0f / (float)PP;
        s.x = (s.x + o.x) * inv;
        s.y = (s.y + o.y) * inv;
        s.z = (s.z + o.z) * inv;
        s.w = (s.w + o.w) * inv;
        ((float4*)(g_framemean + n * DD))[col] = s;
    }
}

// ---------------------------------------------------------------------------
// K2: windowed-parallel momentum EMA scan (0.5^40 truncation ~9e-13)
// ---------------------------------------------------------------------------
#define SCAN_SEG 8
#define SCAN_WIN 40
__global__ void __launch_bounds__(384) scan_kernel() {
    int b = blockIdx.x;
    int s = b * SCAN_SEG;
    int c4 = threadIdx.x;                     // float4 col 0..383
    const float4* fm = (const float4*)g_framemean;
    float4* mom = (float4*)g_mommean;

    float4 m;
    int istart;
    if (b == 0) {
        float4 f0 = fm[c4];
        float4 f1 = fm[384 + c4];
        m = make_float4(f1.x - f0.x, f1.y - f0.y, f1.z - f0.z, f1.w - f0.w);
        mom[c4] = m;
        istart = 1;
    } else {
        int istar = s - 1;
        int jlo = istar - (SCAN_WIN - 1); if (jlo < 0) jlo = 0;
        float w = 0.5f;
        float4 acc = make_float4(0.f, 0.f, 0.f, 0.f);
#pragma unroll 8
        for (int j = istar; j >= jlo; j--) {
            float4 fa = fm[(size_t)j * 384 + c4];
            float4 fb = fm[(size_t)(j + 1) * 384 + c4];
            acc.x = fmaf(w, fb.x - fa.x, acc.x);
            acc.y = fmaf(w, fb.y - fa.y, acc.y);
            acc.z = fmaf(w, fb.z - fa.z, acc.z);
            acc.w = fmaf(w, fb.w - fa.w, acc.w);
            if (j >= 2) w *= 0.5f;            // diff[0] shares diff[1]'s weight
        }
        m = acc;
        istart = s;
    }
#pragma unroll
    for (int i0 = 0; i0 < SCAN_SEG; i0++) {
        int i = (b == 0) ? (istart + i0) : (s + i0);
        if (i >= NM1) break;
        if (b == 0 && i0 >= SCAN_SEG - 1 && istart + i0 >= SCAN_SEG) break;
        if (i < istart) continue;
        float4 fa = fm[(size_t)i * 384 + c4];
        float4 fb = fm[(size_t)(i + 1) * 384 + c4];
        m.x = 0.5f * (fb.x - fa.x) + 0.5f * m.x;
        m.y = 0.5f * (fb.y - fa.y) + 0.5f * m.y;
        m.z = 0.5f * (fb.z - fa.z) + 0.5f * m.z;
        m.w = 0.5f * (fb.w - fa.w) + 0.5f * m.w;
        mom[(size_t)i * 384 + c4] = m;
    }
}

// ---------------------------------------------------------------------------
// tf32 tensor-core split-K GEMM with hi/lo error compensation.
// BM=64, BN=64, BK=32 (halved barrier count vs BK=16), 256 threads,
// 8 warps (4 m x 2 n), each warp 16x32 output, 3 mma per n8 tile (hh,hl,lh).
// ---------------------------------------------------------------------------
#define GBM 64
#define GBN 64
#define GBK 32
#define ASTR (GBK + 4)    // 36
#define BSTR (GBN + 4)    // 68

__global__ void __launch_bounds__(256) gemm_tf32_splitk(
    const float* __restrict__ A, const float* __restrict__ B,
    float* __restrict__ Cpart, int M, int N, int K)
{
    __shared__ float As_hi[2][GBM][ASTR];
    __shared__ float As_lo[2][GBM][ASTR];
    __shared__ float Bs_hi[2][GBK][BSTR];
    __shared__ float Bs_lo[2][GBK][BSTR];

    int tid = threadIdx.x;
    int lane = tid & 31, wid = tid >> 5;
    int wm = (wid & 3) * 16;
    int wn = (wid >> 2) * 32;
    int g = lane >> 2, t = lane & 3;

    int n0 = blockIdx.x * GBN;
    int m0 = blockIdx.y * GBM;
    int kchunk = K / gridDim.z;
    int k0 = blockIdx.z * kchunk;
    int ksteps = kchunk / GBK;

    // tile-load mapping: A 64x32 (2 float4/thread), B 32x64 (2 float4/thread)
    int ar = tid >> 2;              // 0..63
    int ac = (tid & 3) * 4;         // 0,4,8,12 ; second at +16
    int br = tid >> 4;              // 0..15    ; second at +16
    int bc = (tid & 15) * 4;        // 0..60

    bool a_ok = (m0 + ar) < M;
    const float* Aptr = A + (size_t)(m0 + ar) * K + k0;
    const float* Bptr = B + (size_t)(k0 + br) * N + n0 + bc;

    float d[4][4];
#pragma unroll
    for (int j = 0; j < 4; j++)
#pragma unroll
        for (int i = 0; i < 4; i++) d[j][i] = 0.f;

    float4 a_pre0, a_pre1, b_pre0, b_pre1;

    auto fetch = [&](int kt) {
        const float* ap = Aptr + kt * GBK;
        a_pre0 = a_ok ? *(const float4*)(ap + ac)      : make_float4(0.f, 0.f, 0.f, 0.f);
        a_pre1 = a_ok ? *(const float4*)(ap + ac + 16) : make_float4(0.f, 0.f, 0.f, 0.f);
        const float* bp = Bptr + (size_t)kt * GBK * N;
        b_pre0 = *(const float4*)bp;
        b_pre1 = *(const float4*)(bp + (size_t)16 * N);
    };
    auto stage = [&](int buf) {
        float4 av = a_pre0;
        float h0 = f2tf32(av.x), h1 = f2tf32(av.y), h2 = f2tf32(av.z), h3 = f2tf32(av.w);
        *(float4*)&As_hi[buf][ar][ac] = make_float4(h0, h1, h2, h3);
        *(float4*)&As_lo[buf][ar][ac] =
            make_float4(f2tf32(av.x - h0), f2tf32(av.y - h1),
                        f2tf32(av.z - h2), f2tf32(av.w - h3));
        av = a_pre1;
        h0 = f2tf32(av.x); h1 = f2tf32(av.y); h2 = f2tf32(av.z); h3 = f2tf32(av.w);
        *(float4*)&As_hi[buf][ar][ac + 16] = make_float4(h0, h1, h2, h3);
        *(float4*)&As_lo[buf][ar][ac + 16] =
            make_float4(f2tf32(av.x - h0), f2tf32(av.y - h1),
                        f2tf32(av.z - h2), f2tf32(av.w - h3));
        float4 bv = b_pre0;
        float p0 = f2tf32(bv.x), p1 = f2tf32(bv.y), p2 = f2tf32(bv.z), p3 = f2tf32(bv.w);
        *(float4*)&Bs_hi[buf][br][bc] = make_float4(p0, p1, p2, p3);
        *(float4*)&Bs_lo[buf][br][bc] =
            make_float4(f2tf32(bv.x - p0), f2tf32(bv.y - p1),
                        f2tf32(bv.z - p2), f2tf32(bv.w - p3));
        bv = b_pre1;
        p0 = f2tf32(bv.x); p1 = f2tf32(bv.y); p2 = f2tf32(bv.z); p3 = f2tf32(bv.w);
        *(float4*)&Bs_hi[buf][br + 16][bc] = make_float4(p0, p1, p2, p3);
        *(float4*)&Bs_lo[buf][br + 16][bc] =
            make_float4(f2tf32(bv.x - p0), f2tf32(bv.y - p1),
                        f2tf32(bv.z - p2), f2tf32(bv.w - p3));
    };

    fetch(0);
    stage(0);
    __syncthreads();

    for (int kt = 0; kt < ksteps; kt++) {
        int cur = kt & 1;
        if (kt + 1 < ksteps) fetch(kt + 1);
#pragma unroll
        for (int ks = 0; ks < 4; ks++) {
            int kk = ks * 8;
            uint32_t ah[4], al[4];
            ah[0] = __float_as_uint(As_hi[cur][wm + g    ][kk + t    ]);
            ah[1] = __float_as_uint(As_hi[cur][wm + g + 8][kk + t    ]);
            ah[2] = __float_as_uint(As_hi[cur][wm + g    ][kk + t + 4]);
            ah[3] = __float_as_uint(As_hi[cur][wm + g + 8][kk + t + 4]);
            al[0] = __float_as_uint(As_lo[cur][wm + g    ][kk + t    ]);
            al[1] = __float_as_uint(As_lo[cur][wm + g + 8][kk + t    ]);
            al[2] = __float_as_uint(As_lo[cur][wm + g    ][kk + t + 4]);
            al[3] = __float_as_uint(As_lo[cur][wm + g + 8][kk + t + 4]);
#pragma unroll
            for (int j = 0; j < 4; j++) {
                int n = wn + j * 8 + g;
                uint32_t bh0 = __float_as_uint(Bs_hi[cur][kk + t    ][n]);
                uint32_t bh1 = __float_as_uint(Bs_hi[cur][kk + t + 4][n]);
                uint32_t bl0 = __float_as_uint(Bs_lo[cur][kk + t    ][n]);
                uint32_t bl1 = __float_as_uint(Bs_lo[cur][kk + t + 4][n]);
                MMA_TF32(d[j], ah, bh0, bh1);   // hi*hi
                MMA_TF32(d[j], ah, bl0, bl1);   // hi*lo
                MMA_TF32(d[j], al, bh0, bh1);   // lo*hi
            }
        }
        if (kt + 1 < ksteps) {
            stage(cur ^ 1);
            __syncthreads();
        }
    }

    size_t MN = (size_t)M * N;
    float* Cb = Cpart + (size_t)blockIdx.z * MN;
#pragma unroll
    for (int j = 0; j < 4; j++) {
        int col = n0 + wn + j * 8 + 2 * t;
        int r0 = m0 + wm + g;
        if (r0 < M) *(float2*)&Cb[(size_t)r0 * N + col] = make_float2(d[j][0], d[j][1]);
        int r1 = r0 + 8;
        if (r1 < M) *(float2*)&Cb[(size_t)r1 * N + col] = make_float2(d[j][2], d[j][3]);
    }
}

// ---------------------------------------------------------------------------
// Fused: combine split-K partials (+b_agg) -> LayerNorm -> g_xn.
// One row/block, 512 threads (3 cols each).
// ---------------------------------------------------------------------------
__global__ void __launch_bounds__(512) ln_combine_kernel(
    const float* __restrict__ part, const float* __restrict__ b_agg,
    const float* __restrict__ ln_g, const float* __restrict__ ln_b)
{
    int row = blockIdx.x;
    const size_t MN = (size_t)NM1 * DD;
    const float* base = part + (size_t)row * DD;
    float v[3];
    float s = 0.f, ss = 0.f;
#pragma unroll
    for (int c = 0; c < 3; c++) {
        int col = threadIdx.x + c * 512;
        float a = b_agg[col];
#pragma unroll
        for (int z = 0; z < SPLITK; z++) a += base[(size_t)z * MN + col];
        v[c] = a;
        s += a;
        ss = fmaf(a, a, ss);
    }
    __shared__ float sh1[16], sh2[16];
    int lane = threadIdx.x & 31, w = threadIdx.x >> 5;
#pragma unroll
    for (int o = 16; o; o >>= 1) {
        s  += __shfl_xor_sync(0xFFFFFFFFu, s, o);
        ss += __shfl_xor_sync(0xFFFFFFFFu, ss, o);
    }
    if (lane == 0) { sh1[w] = s; sh2[w] = ss; }
    __syncthreads();
    if (w == 0) {
        s  = (lane < 16) ? sh1[lane] : 0.f;
        ss = (lane < 16) ? sh2[lane] : 0.f;
#pragma unroll
        for (int o = 8; o; o >>= 1) {
            s  += __shfl_xor_sync(0xFFFFFFFFu, s, o);
            ss += __shfl_xor_sync(0xFFFFFFFFu, ss, o);
        }
        if (lane == 0) { sh1[0] = s; sh2[0] = ss; }
    }
    __syncthreads();
    float mu  = sh1[0] * (1.0f / DD);
    float var = sh2[0] * (1.0f / DD) - mu * mu;
    float rstd = rsqrtf(var + 1e-5f);
#pragma unroll
    for (int c = 0; c < 3; c++) {
        int col = threadIdx.x + c * 512;
        g_xn[row * DD + col] = (v[c] - mu) * rstd * ln_g[col] + ln_b[col];
    }
}

// ---------------------------------------------------------------------------
// Fused: combine split-K partials (+b1) -> GELU -> dot W2 (+b2) ->
// gate logits (out) + gumbel-softmax y (g_y). One row/block, 512 threads.
// ---------------------------------------------------------------------------
__global__ void __launch_bounds__(512) gate_combine_kernel(
    const float* __restrict__ part, const float* __restrict__ b1,
    const float* __restrict__ W2, const float* __restrict__ b2,
    const float* __restrict__ gu, float* __restrict__ out)
{
    int row = blockIdx.x;
    const size_t MN = (size_t)NM1 * DD;
    const float* base = part + (size_t)row * DD;
    float s0 = 0.f, s1 = 0.f;
#pragma unroll
    for (int c = 0; c < 3; c++) {
        int col = threadIdx.x + c * 512;
        float a = b1[col];
#pragma unroll
        for (int z = 0; z < SPLITK; z++) a += base[(size_t)z * MN + col];
        a = 0.5f * a * (1.0f + erff(a * 0.70710678118654752f));   // exact GELU
        float2 w2 = *(const float2*)&W2[col * 2];
        s0 = fmaf(a, w2.x, s0);
        s1 = fmaf(a, w2.y, s1);
    }
    __shared__ float sh0[16], sh1w[16];
    int lane = threadIdx.x & 31, w = threadIdx.x >> 5;
#pragma unroll
    for (int o = 16; o; o >>= 1) {
        s0 += __shfl_xor_sync(0xFFFFFFFFu, s0, o);
        s1 += __shfl_xor_sync(0xFFFFFFFFu, s1, o);
    }
    if (lane == 0) { sh0[w] = s0; sh1w[w] = s1; }
    __syncthreads();
    if (threadIdx.x == 0) {
        float l0 = b2[0], l1 = b2[1];
#pragma unroll
        for (int i = 0; i < 16; i++) { l0 += sh0[i]; l1 += sh1w[i]; }
        out[OUT_GATE + row * 2 + 0] = l0;
        out[OUT_GATE + row * 2 + 1] = l1;
        float u0 = gu[row * 2 + 0], u1 = gu[row * 2 + 1];
        float g0 = -logf(-logf(u0 + 1e-20f) + 1e-20f);
        float g1 = -logf(-logf(u1 + 1e-20f) + 1e-20f);
        float a0 = (l0 + g0 * 0.1f) * 2.0f;   // / TEMP(0.5)
        float a1 = (l1 + g1 * 0.1f) * 2.0f;
        float mx = fmaxf(a0, a1);
        float e0 = expf(a0 - mx), e1 = expf(a1 - mx);
        g_y[row] = e1 / (e0 + e1);
    }
}

// ---------------------------------------------------------------------------
// Top-8 selection (stable), z_hard, weights
// ---------------------------------------------------------------------------
__global__ void __launch_bounds__(128) topk_kernel(float* __restrict__ out) {
    __shared__ float yv[128];
    __shared__ float rv[128];
    __shared__ int   ri[128];
    __shared__ int   taken[128];
    int t = threadIdx.x;
    yv[t] = (t < NM1) ? g_y[t] : -1e30f;
    taken[t] = 0;
    __syncthreads();
    for (int it = 0; it < NCUBES; it++) {
        rv[t] = taken[t] ? -1e30f : yv[t];
        ri[t] = t;
        __syncthreads();
        for (int off = 64; off > 0; off >>= 1) {
            if (t < off) {
                float v2 = rv[t + off]; int i2 = ri[t + off];
                if (v2 > rv[t] || (v2 == rv[t] && i2 < ri[t])) { rv[t] = v2; ri[t] = i2; }
            }
            __syncthreads();
        }
        if (t == 0) taken[ri[0]] = 1;
        __syncthreads();
    }
    float z = 0.f;
    if (t < NM1) z = taken[t] ? ((1.0f - yv[t]) + yv[t]) : 0.0f;
    if (t == 0) out[OUT_Z] = 1.0f;
    if (t < NM1) out[OUT_Z + 1 + t] = z;
    rv[t] = z;
    __syncthreads();
    for (int off = 64; off > 0; off >>= 1) {
        if (t < off) rv[t] += rv[t + off];
        __syncthreads();
    }
    if (t == 0) {
        float zsum = 1.0f + rv[0];
        g_scale = 1.0f / ((float)PG * zsum);
        g_selidx[0] = 0; g_selw[0] = 1.0f;
        int c = 1;
        for (int i = 0; i < NM1; i++) {
            if (taken[i]) {
                g_selidx[c] = i + 1;
                g_selw[c] = (1.0f - yv[i]) + yv[i];
                c++;
            }
        }
    }
}

// ---------------------------------------------------------------------------
// pooled[g][d] = scale * sum_k w_k * sum_{p in group g} vf[sel_k][p][d]
// ---------------------------------------------------------------------------
__global__ void __launch_bounds__(128) pooled_kernel(const float* __restrict__ vf) {
    int g = blockIdx.x;
    int d4 = blockIdx.y * 128 + threadIdx.x;   // 0..383
    // hoist selection into registers once
    int   sidx[PG];
    float sw[PG];
#pragma unroll
    for (int k = 0; k < PG; k++) { sidx[k] = g_selidx[k]; sw[k] = g_selw[k]; }
    float4 acc = make_float4(0.f, 0.f, 0.f, 0.f);
#pragma unroll
    for (int k = 0; k < PG; k++) {
        const float4* base =
            (const float4*)(vf + ((size_t)sidx[k] * PP + (size_t)g * PG) * DD) + d4;
        float w = sw[k];
#pragma unroll
        for (int r = 0; r < PG; r++) {
            float4 v = base[(size_t)r * (DD / 4)];
            acc.x = fmaf(w, v.x, acc.x);
            acc.y = fmaf(w, v.y, acc.y);
            acc.z = fmaf(w, v.z, acc.z);
            acc.w = fmaf(w, v.w, acc.w);
        }
    }
    float sc = g_scale;
    acc.x *= sc; acc.y *= sc; acc.z *= sc; acc.w *= sc;
    ((float4*)(g_pooled + g * DD))[d4] = acc;
}

// ---------------------------------------------------------------------------
// Thumbnail combine (SPLITK3 partials): float2-vectorized
// ---------------------------------------------------------------------------
__global__ void __launch_bounds__(256) combine_th_kernel(
    const float* __restrict__ part, const float* __restrict__ bias,
    float* __restrict__ dst)
{
    int idx = blockIdx.x * blockDim.x + threadIdx.x;   // float2 index
    const int total2 = NQ * LM / 2;
    if (idx >= total2) return;
    int col2 = idx & (LM / 2 - 1);
    float2 v = *(const float2*)&bias[col2 * 2];
    const float2* p2 = (const float2*)part;
#pragma unroll
    for (int z = 0; z < SPLITK3; z++) {
        float2 a = p2[(size_t)z * total2 + idx];
        v.x += a.x; v.y += a.y;
    }
    *(float2*)&dst[idx * 2] = v;
}

// ---------------------------------------------------------------------------
// launch
// ---------------------------------------------------------------------------
extern "C" void kernel_launch(void* const* d_in, const int* in_sizes, int n_in,
                              void* d_out, int out_size) {
    const float* vf    = (const float*)d_in[0];
    const float* gu    = (const float*)d_in[1];
    const float* W_agg = (const float*)d_in[2];
    const float* b_agg = (const float*)d_in[3];
    const float* ln_g  = (const float*)d_in[4];
    const float* ln_b  = (const float*)d_in[5];
    const float* W1    = (const float*)d_in[6];
    const float* b1    = (const float*)d_in[7];
    const float* W2    = (const float*)d_in[8];
    const float* b2    = (const float*)d_in[9];
    const float* W_th  = (const float*)d_in[10];
    const float* b_th  = (const float*)d_in[11];
    float* out = (float*)d_out;

    float* d_part;   cudaGetSymbolAddress((void**)&d_part,   g_part);
    float* d_mom;    cudaGetSymbolAddress((void**)&d_mom,    g_mommean);
    float* d_xn;     cudaGetSymbolAddress((void**)&d_xn,     g_xn);
    float* d_pooled; cudaGetSymbolAddress((void**)&d_pooled, g_pooled);

    // 1) stream video features once -> framemean
    framesum_kernel<<<dim3(NF, 3), 256>>>(vf);
    // 2) windowed-parallel momentum EMA scan
    scan_kernel<<<16, 384>>>();
    // 3) feat partials = mommean @ W_agg   (tf32 TC, split-K=8)
    gemm_tf32_splitk<<<dim3(DD / GBN, 2, SPLITK), 256>>>(d_mom, W_agg, d_part, NM1, DD, DD);
    // 4) combine + bias + LayerNorm -> xn
    ln_combine_kernel<<<NM1, 512>>>(d_part, b_agg, ln_g, ln_b);
    // 5) h partials = xn @ W1
    gemm_tf32_splitk<<<dim3(DD / GBN, 2, SPLITK), 256>>>(d_xn, W1, d_part, NM1, DD, DD);
    // 6) combine + bias + GELU + gate head + gumbel y
    gate_combine_kernel<<<NM1, 512>>>(d_part, b1, W2, b2, gu, out);
    // 7) top-8 + z_hard
    topk_kernel<<<1, 128>>>(out);
    // 8) pooled from selected frames (direct vf gather)
    pooled_kernel<<<dim3(NQ, 3), 128>>>(vf);
    // 9) thumbnail partials = pooled @ W_th  (split-K=4)
    gemm_tf32_splitk<<<dim3(LM / GBN, 1, SPLITK3), 256>>>(d_pooled, W_th, d_part, NQ, LM, DD);
    // 10) combine + bias -> out
    combine_th_kernel<<<(NQ * LM / 2 + 255) / 256, 256>>>(d_part, b_th, out + OUT_TH);
}